// round 1
// baseline (speedup 1.0000x reference)
#include <cuda_runtime.h>
#include <cuda_bf16.h>
#include <cstddef>

// Problem constants
#define V    4096
#define D    128
#define KS   3
#define NH   4
#define HD   32
#define FF   128
#define NL   2
#define NVIS 8192
#define MAXC 32

// ---------------- scratch (device globals; no allocation allowed) ----------
__device__ float g_Z0[V * D];          // logmap0 output
__device__ float g_Y[KS * V * D];      // Yk = Z0 @ Wk^T
__device__ float g_X[V * D];           // current hidden state
__device__ float g_qkv[V * 3 * D];     // qkv projections
__device__ float g_attn[V * D];        // attention output (pre-Wo)
__device__ float g_tmp[V * D];         // pre-layernorm residual sum
__device__ float g_ff[V * FF];         // ff hidden

// ---------------- logmap0 ---------------------------------------------------
__global__ void k_logmap0(const float* __restrict__ X, float* __restrict__ Z) {
    __shared__ float red[128];
    int row = blockIdx.x, d = threadIdx.x;
    float x = X[row * D + d];
    red[d] = x * x;
    __syncthreads();
    for (int s = 64; s > 0; s >>= 1) {
        if (d < s) red[d] += red[d + s];
        __syncthreads();
    }
    float norm = sqrtf(red[0]);
    float nc = fminf(fmaxf(norm, 1e-7f), 1.0f - 1e-5f);
    float at = 0.5f * logf((1.0f + nc) / (1.0f - nc));  // artanh
    float sc = at / fmaxf(norm, 1e-7f);
    Z[row * D + d] = sc * x;
}

// ---------------- generic tiled fp32 GEMM ----------------------------------
// C[m,n] = sum_k A[m,k]*B[k,n]  (+bias[n]) (+residual[m,n]) (optional gelu)
// A addressed via (rsA, csA); B via (rsB, csB); C row-major with ld = N.
// Requires M%64==0, N%64==0, Kdim%32==0 (true for all uses here).
#define BM 64
#define BN 64
#define BK 32

__global__ __launch_bounds__(256) void k_gemm(
    const float* __restrict__ A, int rsA, int csA,
    const float* __restrict__ B, int rsB, int csB,
    float* __restrict__ C, int N, int Kdim,
    const float* __restrict__ bias,
    const float* __restrict__ residual,
    int gelu_flag)
{
    __shared__ float As[BK][BM + 4];
    __shared__ float Bs[BK][BN + 4];

    int tid = threadIdx.x;            // 256 threads
    int tx = tid & 15, ty = tid >> 4; // 16x16 thread grid, 4x4 micro-tile
    int m0 = blockIdx.y * BM;
    int n0 = blockIdx.x * BN;

    float acc[4][4] = {};

    for (int k0 = 0; k0 < Kdim; k0 += BK) {
        // load A tile (kk fastest => contiguous when csA==1)
        #pragma unroll
        for (int i = 0; i < 8; i++) {
            int idx = tid + i * 256;
            int kk = idx & (BK - 1);
            int m  = idx >> 5;
            As[kk][m] = A[(size_t)(m0 + m) * rsA + (size_t)(k0 + kk) * csA];
        }
        // load B tile
        if (csB == 1) {
            #pragma unroll
            for (int i = 0; i < 8; i++) {
                int idx = tid + i * 256;
                int n  = idx & (BN - 1);
                int kk = idx >> 6;
                Bs[kk][n] = B[(size_t)(k0 + kk) * rsB + (size_t)(n0 + n)];
            }
        } else {
            #pragma unroll
            for (int i = 0; i < 8; i++) {
                int idx = tid + i * 256;
                int kk = idx & (BK - 1);
                int n  = idx >> 5;
                Bs[kk][n] = B[(size_t)(k0 + kk) * rsB + (size_t)(n0 + n) * csB];
            }
        }
        __syncthreads();

        #pragma unroll
        for (int kk = 0; kk < BK; kk++) {
            float4 a4 = *(const float4*)&As[kk][ty * 4];
            float4 b4 = *(const float4*)&Bs[kk][tx * 4];
            float av[4] = {a4.x, a4.y, a4.z, a4.w};
            float bv[4] = {b4.x, b4.y, b4.z, b4.w};
            #pragma unroll
            for (int i = 0; i < 4; i++)
                #pragma unroll
                for (int j = 0; j < 4; j++)
                    acc[i][j] += av[i] * bv[j];
        }
        __syncthreads();
    }

    #pragma unroll
    for (int i = 0; i < 4; i++) {
        int m = m0 + ty * 4 + i;
        #pragma unroll
        for (int j = 0; j < 4; j++) {
            int n = n0 + tx * 4 + j;
            float v = acc[i][j];
            if (bias) v += bias[n];
            if (residual) v += residual[(size_t)m * N + n];
            if (gelu_flag) {
                float x = v;
                float t = tanhf(0.7978845608028654f * (x + 0.044715f * x * x * x));
                v = 0.5f * x * (1.0f + t);
            }
            C[(size_t)m * N + n] = v;
        }
    }
}

// ---------------- flash attention (hd=32, H=4, V=4096) ---------------------
// one thread per (query, head); online softmax; K/V tiles staged in smem.
__global__ __launch_bounds__(128) void k_attn(const float* __restrict__ qkv,
                                              float* __restrict__ O)
{
    __shared__ float Ksm[128][HD];
    __shared__ float Vsm[128][HD];

    int h = blockIdx.y;
    int q = blockIdx.x * 128 + threadIdx.x;
    int warp = threadIdx.x >> 5, lane = threadIdx.x & 31;
    const float scale = 0.17677669529663687f;  // 1/sqrt(32)

    float qv[HD];
    const float* qp = qkv + (size_t)q * 3 * D + h * HD;
    #pragma unroll
    for (int e = 0; e < HD; e++) qv[e] = qp[e];

    float m = -1e30f, l = 0.0f;
    float o[HD];
    #pragma unroll
    for (int e = 0; e < HD; e++) o[e] = 0.0f;

    for (int t0 = 0; t0 < V; t0 += 128) {
        __syncthreads();
        // each warp loads 32 rows; lane = element index (coalesced 128B/row)
        #pragma unroll 4
        for (int r = 0; r < 32; r++) {
            int row = warp * 32 + r;
            size_t base = (size_t)(t0 + row) * (3 * D) + h * HD + lane;
            Ksm[row][lane] = qkv[base + D];
            Vsm[row][lane] = qkv[base + 2 * D];
        }
        __syncthreads();

        for (int t = 0; t < 128; t++) {
            const float4* kp = (const float4*)Ksm[t];
            float s = 0.0f;
            #pragma unroll
            for (int e4 = 0; e4 < 8; e4++) {
                float4 kk = kp[e4];
                s += qv[4 * e4 + 0] * kk.x + qv[4 * e4 + 1] * kk.y +
                     qv[4 * e4 + 2] * kk.z + qv[4 * e4 + 3] * kk.w;
            }
            s *= scale;
            if (s > m) {
                float c = __expf(m - s);
                l *= c;
                #pragma unroll
                for (int e = 0; e < HD; e++) o[e] *= c;
                m = s;
            }
            float p = __expf(s - m);
            l += p;
            const float4* vp = (const float4*)Vsm[t];
            #pragma unroll
            for (int e4 = 0; e4 < 8; e4++) {
                float4 vv = vp[e4];
                o[4 * e4 + 0] += p * vv.x;
                o[4 * e4 + 1] += p * vv.y;
                o[4 * e4 + 2] += p * vv.z;
                o[4 * e4 + 3] += p * vv.w;
            }
        }
    }

    float inv = 1.0f / l;
    float* op = O + (size_t)q * D + h * HD;
    #pragma unroll
    for (int e = 0; e < HD; e++) op[e] = o[e] * inv;
}

// ---------------- layernorm (per row of 128) --------------------------------
__global__ void k_ln(const float* __restrict__ in, const float* __restrict__ g,
                     const float* __restrict__ b, float* __restrict__ out)
{
    __shared__ float red[128];
    int row = blockIdx.x, d = threadIdx.x;
    float x = in[row * D + d];
    red[d] = x;
    __syncthreads();
    for (int s = 64; s > 0; s >>= 1) {
        if (d < s) red[d] += red[d + s];
        __syncthreads();
    }
    float mean = red[0] * (1.0f / 128.0f);
    __syncthreads();
    float c = x - mean;
    red[d] = c * c;
    __syncthreads();
    for (int s = 64; s > 0; s >>= 1) {
        if (d < s) red[d] += red[d + s];
        __syncthreads();
    }
    float var = red[0] * (1.0f / 128.0f);
    out[row * D + d] = c * rsqrtf(var + 1e-5f) * g[d] + b[d];
}

// ---------------- per-visit masked mean pooling ------------------------------
__global__ void k_pool(const int* __restrict__ visits,
                       const float* __restrict__ Xf, float* __restrict__ out)
{
    int vis = blockIdx.x, d = threadIdx.x;
    float s = 0.0f;
    int cnt = 0;
    #pragma unroll 8
    for (int c = 0; c < MAXC; c++) {
        int code = visits[vis * MAXC + c];
        if (code != 0) {
            cnt++;
            s += Xf[(size_t)code * D + d];
        }
    }
    out[(size_t)vis * D + d] = (cnt > 0) ? (s / (float)cnt) : 0.0f;
}

// ---------------- host orchestration ----------------------------------------
extern "C" void kernel_launch(void* const* d_in, const int* in_sizes, int n_in,
                              void* d_out, int out_size)
{
    const int*   visits  = (const int*)d_in[0];
    const float* X_hyp   = (const float*)d_in[1];
    const float* kernels = (const float*)d_in[2];
    const float* proj_W  = (const float*)d_in[3];
    const float* proj_b  = (const float*)d_in[4];
    const float* Wqkv    = (const float*)d_in[5];
    const float* bqkv    = (const float*)d_in[6];
    const float* Wo      = (const float*)d_in[7];
    const float* bo      = (const float*)d_in[8];
    const float* W1      = (const float*)d_in[9];
    const float* b1      = (const float*)d_in[10];
    const float* W2      = (const float*)d_in[11];
    const float* b2      = (const float*)d_in[12];
    const float* ln1_g   = (const float*)d_in[13];
    const float* ln1_b   = (const float*)d_in[14];
    const float* ln2_g   = (const float*)d_in[15];
    const float* ln2_b   = (const float*)d_in[16];
    float* out = (float*)d_out;

    float *pZ0, *pY, *pX, *pqkv, *pattn, *ptmp, *pff;
    cudaGetSymbolAddress((void**)&pZ0,   g_Z0);
    cudaGetSymbolAddress((void**)&pY,    g_Y);
    cudaGetSymbolAddress((void**)&pX,    g_X);
    cudaGetSymbolAddress((void**)&pqkv,  g_qkv);
    cudaGetSymbolAddress((void**)&pattn, g_attn);
    cudaGetSymbolAddress((void**)&ptmp,  g_tmp);
    cudaGetSymbolAddress((void**)&pff,   g_ff);

    // 1) logmap0
    k_logmap0<<<V, 128>>>(X_hyp, pZ0);

    // 2) Yk = Z0 @ Wk^T  (Wk = proj_W[:, k*D:(k+1)*D], proj_W is [D, 3D])
    for (int k = 0; k < KS; k++) {
        k_gemm<<<dim3(D / BN, V / BM), 256>>>(
            pZ0, D, 1,
            proj_W + k * D, 1, KS * D,
            pY + (size_t)k * V * D, D, D,
            nullptr, nullptr, 0);
    }

    // 3) X = proj_b + sum_k kernels[k] @ Yk
    for (int k = 0; k < KS; k++) {
        k_gemm<<<dim3(D / BN, V / BM), 256>>>(
            kernels + (size_t)k * V * V, V, 1,
            pY + (size_t)k * V * D, D, 1,
            pX, D, V,
            (k == 0) ? proj_b : nullptr,
            (k == 0) ? nullptr : pX, 0);
    }

    // 4) transformer layers
    for (int l = 0; l < NL; l++) {
        // qkv = X @ Wqkv^T + bqkv
        k_gemm<<<dim3((3 * D) / BN, V / BM), 256>>>(
            pX, D, 1,
            Wqkv + (size_t)l * 3 * D * D, 1, D,
            pqkv, 3 * D, D,
            bqkv + l * 3 * D, nullptr, 0);

        // attention -> g_attn
        k_attn<<<dim3(V / 128, NH), 128>>>(pqkv, pattn);

        // tmp = X + attn @ Wo^T + bo
        k_gemm<<<dim3(D / BN, V / BM), 256>>>(
            pattn, D, 1,
            Wo + (size_t)l * D * D, 1, D,
            ptmp, D, D,
            bo + l * D, pX, 0);

        // X = LN1(tmp)
        k_ln<<<V, 128>>>(ptmp, ln1_g + l * D, ln1_b + l * D, pX);

        // ff = gelu(X @ W1^T + b1)
        k_gemm<<<dim3(FF / BN, V / BM), 256>>>(
            pX, D, 1,
            W1 + (size_t)l * FF * D, 1, D,
            pff, FF, D,
            b1 + l * FF, nullptr, 1);

        // tmp = X + ff @ W2^T + b2
        k_gemm<<<dim3(D / BN, V / BM), 256>>>(
            pff, FF, 1,
            W2 + (size_t)l * D * FF, 1, FF,
            ptmp, D, FF,
            b2 + l * D, pX, 0);

        // X = LN2(tmp)
        k_ln<<<V, 128>>>(ptmp, ln2_g + l * D, ln2_b + l * D, pX);
    }

    // 5) pooling
    k_pool<<<NVIS, 128>>>(visits, pX, out);
}